// round 15
// baseline (speedup 1.0000x reference)
#include <cuda_runtime.h>
#include <cstdint>

#define IN_H   1024
#define IN_W   1024
#define OUT_H  256
#define OUT_W  256
#define NTAP   16

#define VCHUNK 8                 // output rows per strip
#define G      4                 // input rows per cp.async group
#define NG     11                // 44 input rows = 11 groups per strip
#define DEPTH  4                 // ring stages (3 groups in flight)
#define STRIPS 2
#define XBLKS  (OUT_H / VCHUNK / STRIPS)   // 16
#define TOTQ   (STRIPS * NG)               // 22
#define NWARPS 8

// dynamic smem: ring[DEPTH][G][IN_W] (64 KB) + edge[8][NWARPS][4] float4 (4 KB)
#define RING_FLOATS (DEPTH * G * IN_W)
#define SMEM_BYTES  (RING_FLOATS * 4 + VCHUNK * NWARPS * 4 * 16)

__device__ __forceinline__ void cp_async16(uint32_t dst_smem, const float* src) {
    asm volatile("cp.async.cg.shared.global [%0], [%1], 16;\n"
                 :: "r"(dst_smem), "l"(src) : "memory");
}
__device__ __forceinline__ void cp_commit() {
    asm volatile("cp.async.commit_group;\n" ::: "memory");
}
template <int N>
__device__ __forceinline__ void cp_wait() {
    asm volatile("cp.async.wait_group %0;\n" :: "n"(N) : "memory");
}

__global__ __launch_bounds__(256, 3)
void bicubic_fused(const float* __restrict__ in, float* __restrict__ out)
{
    constexpr float W[NTAP] = {
        -0.001708984375f, -0.010986328125f, -0.018310546875f, -0.011962890625f,
         0.022705078125f,  0.097412109375f,  0.181884765625f,  0.240966796875f,
         0.240966796875f,  0.181884765625f,  0.097412109375f,  0.022705078125f,
        -0.011962890625f, -0.018310546875f, -0.010986328125f, -0.001708984375f };
    // clamped-edge combined weights
    constexpr float S06   = W[0]+W[1]+W[2]+W[3]+W[4]+W[5]+W[6];
    constexpr float S02   = W[0]+W[1]+W[2];
    constexpr float S1315 = W[13]+W[14]+W[15];
    constexpr float S915  = W[9]+W[10]+W[11]+W[12]+W[13]+W[14]+W[15];

    extern __shared__ __align__(16) float smem[];
    float (*ring)[G][IN_W] = (float (*)[G][IN_W])smem;                 // 64 KB
    float4 (*edge)[NWARPS][4] = (float4 (*)[NWARPS][4])(smem + RING_FLOATS); // 4 KB

    const int tid = threadIdx.x;                 // owns float4 column tid
    const int w   = tid >> 5;
    const int l   = tid & 31;
    const int img = blockIdx.y;
    const float* __restrict__ inp = in + (size_t)img * (IN_H * IN_W);

    // issue group q (global counter across both strips) into ring[q%DEPTH]
    auto issue = [&](int q) {
        const int s     = q / NG;
        const int g     = q % NG;
        const int strip = blockIdx.x + XBLKS * s;
        const int R0    = 4 * strip * VCHUNK - 6;
#pragma unroll
        for (int r = 0; r < G; ++r) {
            const int gr = min(max(R0 + 4 * g + r, 0), IN_H - 1);
            const uint32_t dst = (uint32_t)__cvta_generic_to_shared(
                &ring[q % DEPTH][r][4 * tid]);
            cp_async16(dst, inp + (size_t)gr * IN_W + 4 * tid);
        }
        cp_commit();
    };

    issue(0); issue(1); issue(2);

    const unsigned FULL = 0xffffffffu;

#pragma unroll
    for (int it = 0; it < STRIPS; ++it) {
        const int strip = blockIdx.x + XBLKS * it;
        const int o0    = strip * VCHUNK;
        float* __restrict__ outp = out + ((size_t)img * OUT_H + o0) * OUT_W;

        float4 acc[VCHUNK];
#pragma unroll
        for (int j = 0; j < VCHUNK; ++j) acc[j] = make_float4(0.f, 0.f, 0.f, 0.f);

        // ---- barrier-free V mainloop; stream continuous across strips ----
#pragma unroll
        for (int g = 0; g < NG; ++g) {
            const int q = it * NG + g;
            if      (q + 3 < TOTQ) { issue(q + 3); cp_wait<3>(); }
            else if (q + 2 < TOTQ) cp_wait<2>();
            else if (q + 1 < TOTQ) cp_wait<1>();
            else                   cp_wait<0>();

            const float4* __restrict__ buf = (const float4*)ring[q % DEPTH];
#pragma unroll
            for (int r = 0; r < G; ++r) {
                const int i = 4 * g + r;
                const float4 x = buf[r * (IN_W / 4) + tid];
#pragma unroll
                for (int j = 0; j < VCHUNK; ++j) {
                    const int k = i - 4 * j;               // compile-time pruned
                    if (k >= 0 && k < NTAP) {
                        acc[j].x = fmaf(W[k], x.x, acc[j].x);
                        acc[j].y = fmaf(W[k], x.y, acc[j].y);
                        acc[j].z = fmaf(W[k], x.z, acc[j].z);
                        acc[j].w = fmaf(W[k], x.w, acc[j].w);
                    }
                }
            }
        }

        // ---- publish warp-boundary accs (lanes 0,1,30,31) ----
#pragma unroll
        for (int j = 0; j < VCHUNK; ++j) {
            if      (l == 0)  edge[j][w][0] = acc[j];
            else if (l == 1)  edge[j][w][1] = acc[j];
            else if (l == 30) edge[j][w][2] = acc[j];
            else if (l == 31) edge[j][w][3] = acc[j];
        }
        __syncthreads();

        // ---- H phase via warp shuffles (no full-row smem) ----
        const int oc = tid;
#pragma unroll
        for (int j = 0; j < VCHUNK; ++j) {
            const float4 c = acc[j];
            float az = __shfl_up_sync(FULL, c.z, 2);
            float aw = __shfl_up_sync(FULL, c.w, 2);
            float bx = __shfl_up_sync(FULL, c.x, 1);
            float by = __shfl_up_sync(FULL, c.y, 1);
            float bz = __shfl_up_sync(FULL, c.z, 1);
            float bw = __shfl_up_sync(FULL, c.w, 1);
            float dx = __shfl_down_sync(FULL, c.x, 1);
            float dy = __shfl_down_sync(FULL, c.y, 1);
            float dz = __shfl_down_sync(FULL, c.z, 1);
            float dw = __shfl_down_sync(FULL, c.w, 1);
            float ex = __shfl_down_sync(FULL, c.x, 2);
            float ey = __shfl_down_sync(FULL, c.y, 2);

            // cross-warp fixes from edge buffer
            if (l < 2 && w > 0) {
                const float4 t = edge[j][w - 1][2 + l];
                az = t.z; aw = t.w;
            }
            if (l == 0 && w > 0) {
                const float4 t = edge[j][w - 1][3];
                bx = t.x; by = t.y; bz = t.z; bw = t.w;
            }
            if (l == 31 && w < NWARPS - 1) {
                const float4 t = edge[j][w + 1][0];
                dx = t.x; dy = t.y; dz = t.z; dw = t.w;
            }
            if (l >= 30 && w < NWARPS - 1) {
                const float4 t = edge[j][w + 1][l - 30];
                ex = t.x; ey = t.y;
            }

            float r;
            if (oc >= 2 && oc <= 253) {
                r = W[0] * az;
                r = fmaf(W[1],  aw,  r);  r = fmaf(W[2],  bx,  r);
                r = fmaf(W[3],  by,  r);  r = fmaf(W[4],  bz,  r);
                r = fmaf(W[5],  bw,  r);  r = fmaf(W[6],  c.x, r);
                r = fmaf(W[7],  c.y, r);  r = fmaf(W[8],  c.z, r);
                r = fmaf(W[9],  c.w, r);  r = fmaf(W[10], dx,  r);
                r = fmaf(W[11], dy,  r);  r = fmaf(W[12], dz,  r);
                r = fmaf(W[13], dw,  r);  r = fmaf(W[14], ex,  r);
                r = fmaf(W[15], ey,  r);
            } else if (oc == 0) {
                // taps k<=6 clamp to col 0 (= c.x)
                r = S06 * c.x;
                r = fmaf(W[7],  c.y, r);  r = fmaf(W[8],  c.z, r);
                r = fmaf(W[9],  c.w, r);  r = fmaf(W[10], dx,  r);
                r = fmaf(W[11], dy,  r);  r = fmaf(W[12], dz,  r);
                r = fmaf(W[13], dw,  r);  r = fmaf(W[14], ex,  r);
                r = fmaf(W[15], ey,  r);
            } else if (oc == 1) {
                // taps k<=2 clamp to col 0 (= bx)
                r = S02 * bx;
                r = fmaf(W[3],  by,  r);  r = fmaf(W[4],  bz,  r);
                r = fmaf(W[5],  bw,  r);  r = fmaf(W[6],  c.x, r);
                r = fmaf(W[7],  c.y, r);  r = fmaf(W[8],  c.z, r);
                r = fmaf(W[9],  c.w, r);  r = fmaf(W[10], dx,  r);
                r = fmaf(W[11], dy,  r);  r = fmaf(W[12], dz,  r);
                r = fmaf(W[13], dw,  r);  r = fmaf(W[14], ex,  r);
                r = fmaf(W[15], ey,  r);
            } else if (oc == 254) {
                // taps k>=13 clamp to col 1023 (= dw)
                r = W[0] * az;
                r = fmaf(W[1],  aw,  r);  r = fmaf(W[2],  bx,  r);
                r = fmaf(W[3],  by,  r);  r = fmaf(W[4],  bz,  r);
                r = fmaf(W[5],  bw,  r);  r = fmaf(W[6],  c.x, r);
                r = fmaf(W[7],  c.y, r);  r = fmaf(W[8],  c.z, r);
                r = fmaf(W[9],  c.w, r);  r = fmaf(W[10], dx,  r);
                r = fmaf(W[11], dy,  r);  r = fmaf(W[12], dz,  r);
                r = fmaf(S1315, dw,  r);
            } else { // oc == 255: taps k>=9 clamp to col 1023 (= c.w)
                r = W[0] * az;
                r = fmaf(W[1],  aw,  r);  r = fmaf(W[2],  bx,  r);
                r = fmaf(W[3],  by,  r);  r = fmaf(W[4],  bz,  r);
                r = fmaf(W[5],  bw,  r);  r = fmaf(W[6],  c.x, r);
                r = fmaf(W[7],  c.y, r);  r = fmaf(W[8],  c.z, r);
                r = fmaf(S915,  c.w, r);
            }
            outp[(size_t)j * OUT_W + oc] = r;
        }
        __syncthreads();                       // edge safe for next strip
    }
}

extern "C" void kernel_launch(void* const* d_in, const int* in_sizes, int n_in,
                              void* d_out, int out_size)
{
    const float* in  = (const float*)d_in[0];
    float*       out = (float*)d_out;

    const int nimg = in_sizes[0] / (IN_H * IN_W);       // 24

    cudaFuncSetAttribute(bicubic_fused,
                         cudaFuncAttributeMaxDynamicSharedMemorySize, SMEM_BYTES);

    dim3 grid(XBLKS, nimg);                             // 16 x 24 = 384 blocks
    bicubic_fused<<<grid, 256, SMEM_BYTES>>>(in, out);
}

// round 16
// speedup vs baseline: 1.1197x; 1.1197x over previous
#include <cuda_runtime.h>
#include <cstdint>

#define IN_H   1024
#define IN_W   1024
#define OUT_H  256
#define OUT_W  256
#define NTAP   16

#define VCHUNK 8                 // output rows per strip
#define G      4                 // input rows per group (2 via cp.async, 2 via LDG)
#define NG     11                // 44 input rows = 11 groups
#define STRIPS 2
#define XBLKS  (OUT_H / VCHUNK / STRIPS)   // 16

// dynamic smem: ring[3][2][IN_W] (24 KB) + v8[8][IN_W] (32 KB) = 56 KB
#define RING_FLOATS (3 * 2 * IN_W)
#define SMEM_BYTES  ((RING_FLOATS + VCHUNK * IN_W) * 4)

__device__ __forceinline__ void cp_async16(uint32_t dst_smem, const float* src) {
    asm volatile("cp.async.cg.shared.global [%0], [%1], 16;\n"
                 :: "r"(dst_smem), "l"(src) : "memory");
}
__device__ __forceinline__ void cp_commit() {
    asm volatile("cp.async.commit_group;\n" ::: "memory");
}
template <int N>
__device__ __forceinline__ void cp_wait() {
    asm volatile("cp.async.wait_group %0;\n" :: "n"(N) : "memory");
}

__global__ __launch_bounds__(256, 3)
void bicubic_fused(const float* __restrict__ in, float* __restrict__ out)
{
    constexpr float W[NTAP] = {
        -0.001708984375f, -0.010986328125f, -0.018310546875f, -0.011962890625f,
         0.022705078125f,  0.097412109375f,  0.181884765625f,  0.240966796875f,
         0.240966796875f,  0.181884765625f,  0.097412109375f,  0.022705078125f,
        -0.011962890625f, -0.018310546875f, -0.010986328125f, -0.001708984375f };

    extern __shared__ __align__(16) float smem[];
    float (*ring)[2][IN_W] = (float (*)[2][IN_W])smem;          // 24 KB
    float (*v8)[IN_W]      = (float (*)[IN_W])(smem + RING_FLOATS);  // 32 KB

    const int tid = threadIdx.x;                 // owns float4 column tid
    const int img = blockIdx.y;
    const float* __restrict__ inp = in + (size_t)img * (IN_H * IN_W);

#pragma unroll 1
    for (int it = 0; it < STRIPS; ++it) {
        const int strip = blockIdx.x + XBLKS * it;       // adjacent strips co-run
        const int o0    = strip * VCHUNK;
        const int R0    = 4 * o0 - 6;
        float* __restrict__ outp = out + ((size_t)img * OUT_H + o0) * OUT_W;

        // cp.async prefetch: rows 0,1 of group g -> ring[g%3]
        auto prefetch = [&](int g) {
#pragma unroll
            for (int r = 0; r < 2; ++r) {
                const int gr = min(max(R0 + 4 * g + r, 0), IN_H - 1);
                const uint32_t dst = (uint32_t)__cvta_generic_to_shared(
                    &ring[g % 3][r][4 * tid]);
                cp_async16(dst, inp + (size_t)gr * IN_W + 4 * tid);
            }
            cp_commit();
        };
        // direct-LDG rows 2,3 of group g
        auto ldg_pair = [&](int g, float4& a, float4& b) {
            const int r2 = min(max(R0 + 4 * g + 2, 0), IN_H - 1);
            const int r3 = min(max(R0 + 4 * g + 3, 0), IN_H - 1);
            a = __ldg((const float4*)(inp + (size_t)r2 * IN_W) + tid);
            b = __ldg((const float4*)(inp + (size_t)r3 * IN_W) + tid);
        };

        prefetch(0);
        prefetch(1);

        float4 lgp[2][2];                        // 2-stage register pipeline
        ldg_pair(0, lgp[0][0], lgp[0][1]);
        ldg_pair(1, lgp[1][0], lgp[1][1]);

        float4 acc[VCHUNK];
#pragma unroll
        for (int j = 0; j < VCHUNK; ++j) acc[j] = make_float4(0.f, 0.f, 0.f, 0.f);

        // ---- barrier-free V mainloop: smem rows 0,1 + register rows 2,3 ----
#pragma unroll
        for (int g = 0; g < NG; ++g) {
            if (g < NG - 1) cp_wait<1>(); else cp_wait<0>();

            // pull register-pipeline rows for this group, then refill stage
            const float4 x2 = lgp[g % 2][0];
            const float4 x3 = lgp[g % 2][1];
            if (g + 2 < NG) {
                prefetch(g + 2);
                ldg_pair(g + 2, lgp[g % 2][0], lgp[g % 2][1]);
            }

            const float4* __restrict__ buf = (const float4*)ring[g % 3];
            const float4 x0 = buf[tid];
            const float4 x1 = buf[(IN_W / 4) + tid];

            const float4 xs[G] = {x0, x1, x2, x3};
#pragma unroll
            for (int r = 0; r < G; ++r) {
                const int i = 4 * g + r;
                const float4 x = xs[r];
#pragma unroll
                for (int j = 0; j < VCHUNK; ++j) {
                    const int k = i - 4 * j;               // compile-time pruned
                    if (k >= 0 && k < NTAP) {
                        acc[j].x = fmaf(W[k], x.x, acc[j].x);
                        acc[j].y = fmaf(W[k], x.y, acc[j].y);
                        acc[j].z = fmaf(W[k], x.z, acc[j].z);
                        acc[j].w = fmaf(W[k], x.w, acc[j].w);
                    }
                }
            }
        }

        // dump acc -> v8
#pragma unroll
        for (int j = 0; j < VCHUNK; ++j)
            ((float4*)v8[j])[tid] = acc[j];
        __syncthreads();                       // publish to other threads

        // ---- H phase: 16-tap; center float4 from registers ----
        const int oc = tid;
#pragma unroll
        for (int j = 0; j < VCHUNK; ++j) {
            const float* __restrict__ srow = v8[j];
            float r;
            if (oc >= 2 && oc <= 253) {
                const float4* __restrict__ sv = (const float4*)srow + oc;
                const float4 a = sv[-2], b = sv[-1], d = sv[1], e = sv[2];
                const float4 c = acc[j];         // own dump, still in registers
                r = W[0] * a.z;                  // tap 0 = v[4oc-6]
                r = fmaf(W[1],  a.w, r);  r = fmaf(W[2],  b.x, r);
                r = fmaf(W[3],  b.y, r);  r = fmaf(W[4],  b.z, r);
                r = fmaf(W[5],  b.w, r);  r = fmaf(W[6],  c.x, r);
                r = fmaf(W[7],  c.y, r);  r = fmaf(W[8],  c.z, r);
                r = fmaf(W[9],  c.w, r);  r = fmaf(W[10], d.x, r);
                r = fmaf(W[11], d.y, r);  r = fmaf(W[12], d.z, r);
                r = fmaf(W[13], d.w, r);  r = fmaf(W[14], e.x, r);
                r = fmaf(W[15], e.y, r);         // tap 15 = v[4oc+9]
            } else {
                r = 0.f;
#pragma unroll
                for (int k = 0; k < NTAP; ++k)
                    r = fmaf(W[k], srow[min(max(4 * oc - 6 + k, 0), IN_W - 1)], r);
            }
            outp[(size_t)j * OUT_W + oc] = r;
        }
        __syncthreads();                       // v8/ring safe for next strip
    }
}

extern "C" void kernel_launch(void* const* d_in, const int* in_sizes, int n_in,
                              void* d_out, int out_size)
{
    const float* in  = (const float*)d_in[0];
    float*       out = (float*)d_out;

    const int nimg = in_sizes[0] / (IN_H * IN_W);       // 24

    cudaFuncSetAttribute(bicubic_fused,
                         cudaFuncAttributeMaxDynamicSharedMemorySize, SMEM_BYTES);

    dim3 grid(XBLKS, nimg);                             // 16 x 24 = 384 blocks
    bicubic_fused<<<grid, 256, SMEM_BYTES>>>(in, out);
}